// round 4
// baseline (speedup 1.0000x reference)
#include <cuda_runtime.h>

#define NNODES 500000
#define CDIM   128
#define HDIM   256
#define ADIM   10
#define BROWS  (NNODES / ADIM)
#define EMAX   600000

// ---------------- scratch (device globals; no allocations allowed) ----------
__device__ __align__(16) float g_xn [(size_t)NNODES * CDIM];  // dinv[row]*(state@W_gcn)
__device__ __align__(16) float g_y  [(size_t)BROWS * CDIM];   // action-weighted readout
__device__ __align__(16) float g_h1 [(size_t)BROWS * HDIM];   // relu(y@W1+b1)
__device__ int   g_deg[NNODES];        // in-degree (w/o self loop)
__device__ float g_dinv[NNODES];
__device__ int   g_rowptr[NNODES];     // CSR row start (by dst)
__device__ int   g_cursor[NNODES];     // fill cursors
__device__ int   g_col[EMAX];          // CSR: src indices
__device__ int   g_bsum[1024];         // scan block sums

// ---------------- small kernels ---------------------------------------------
__global__ void zero_deg_kernel(int n) {
    int i = blockIdx.x * blockDim.x + threadIdx.x;
    if (i < n) g_deg[i] = 0;
}

__global__ void count_deg_kernel(const int* __restrict__ dst, int E, int N) {
    int e = blockIdx.x * blockDim.x + threadIdx.x;
    if (e < E) {
        int d = dst[e];
        if (d >= 0 && d < N) atomicAdd(&g_deg[d], 1);
    }
}

__global__ void dinv_kernel(int n) {
    int i = blockIdx.x * blockDim.x + threadIdx.x;
    if (i < n) g_dinv[i] = rsqrtf((float)(g_deg[i] + 1));  // +1 self-loop
}

__global__ void init_out_kernel(float* __restrict__ out, const float* __restrict__ b3, int B) {
    int i = blockIdx.x * blockDim.x + threadIdx.x;
    if (i < B) out[i] = b3[0];
}

// ---------------- 3-kernel exclusive prefix scan of g_deg -> g_rowptr --------
__global__ void __launch_bounds__(256) scan1_kernel(int n) {
    __shared__ int warp_sums[8];
    const int tid  = threadIdx.x;
    const int lane = tid & 31;
    const int wid  = tid >> 5;
    const int gbase = blockIdx.x * 1024 + tid * 4;

    int v[4];
    int t = 0;
#pragma unroll
    for (int j = 0; j < 4; j++) {
        v[j] = (gbase + j < n) ? g_deg[gbase + j] : 0;
        t += v[j];
    }
    int inc = t;
#pragma unroll
    for (int o = 1; o < 32; o <<= 1) {
        int x = __shfl_up_sync(0xffffffffu, inc, o);
        if (lane >= o) inc += x;
    }
    if (lane == 31) warp_sums[wid] = inc;
    __syncthreads();
    if (wid == 0) {
        int ws = (lane < 8) ? warp_sums[lane] : 0;
#pragma unroll
        for (int o = 1; o < 8; o <<= 1) {
            int x = __shfl_up_sync(0xffffffffu, ws, o);
            if (lane >= o) ws += x;
        }
        if (lane < 8) warp_sums[lane] = ws;
    }
    __syncthreads();
    int block_excl = (wid > 0) ? warp_sums[wid - 1] : 0;
    int run = block_excl + inc - t;   // exclusive prefix for this thread
#pragma unroll
    for (int j = 0; j < 4; j++) {
        if (gbase + j < n) g_rowptr[gbase + j] = run;
        run += v[j];
    }
    if (tid == 0) g_bsum[blockIdx.x] = warp_sums[7];
}

__global__ void __launch_bounds__(512) scan2_kernel(int nb) {
    __shared__ int sh[512];
    const int tid = threadIdx.x;
    int v = (tid < nb) ? g_bsum[tid] : 0;
    sh[tid] = v;
    __syncthreads();
    for (int o = 1; o < 512; o <<= 1) {
        int x = (tid >= o) ? sh[tid - o] : 0;
        __syncthreads();
        sh[tid] += x;
        __syncthreads();
    }
    if (tid < nb) g_bsum[tid] = sh[tid] - v;   // exclusive
}

__global__ void __launch_bounds__(256) scan3_kernel(int n) {
    const int gbase = blockIdx.x * 1024 + threadIdx.x * 4;
    const int off = g_bsum[blockIdx.x];
#pragma unroll
    for (int j = 0; j < 4; j++) {
        int i = gbase + j;
        if (i < n) {
            int r = g_rowptr[i] + off;
            g_rowptr[i] = r;
            g_cursor[i] = r;
        }
    }
}

// fill CSR: col[pos] = src, bucketed by dst
__global__ void fill_kernel(const int* __restrict__ src,
                            const int* __restrict__ dst, int E, int N) {
    int e = blockIdx.x * blockDim.x + threadIdx.x;
    if (e >= E) return;
    int d = dst[e];
    int s = src[e];
    if (d < 0 || d >= N || s < 0 || s >= N) return;
    int pos = atomicAdd(&g_cursor[d], 1);
    if (pos >= 0 && pos < EMAX) g_col[pos] = s;
}

// ---------------- generic tiled fp32 GEMM core -------------------------------
// Block: 256 threads. Tile: 64 rows x 128 cols. BK = 32.
// Thread (rg = tid>>5, cg = tid&31) owns 8 rows x 4 cols.
template <int K, int NW>
__device__ __forceinline__ void gemm_core(const float* __restrict__ A,
                                          const float* __restrict__ W,
                                          int m0, int n0, int M,
                                          float acc[8][4])
{
    __shared__ __align__(16) float As[32][64];    // [k][m]  (transposed)
    __shared__ __align__(16) float Ws[32][128];   // [k][n]

    const int tid = threadIdx.x;
    const int rg  = tid >> 5;
    const int cg  = tid & 31;

#pragma unroll
    for (int i = 0; i < 8; i++)
#pragma unroll
        for (int j = 0; j < 4; j++) acc[i][j] = 0.f;

    for (int kb = 0; kb < K; kb += 32) {
#pragma unroll
        for (int i = 0; i < 2; i++) {
            int f  = tid * 2 + i;          // 0..511 float4 slots
            int m  = f & 63;
            int k4 = f >> 6;               // 0..7
            int row = m0 + m;
            float4 v = make_float4(0.f, 0.f, 0.f, 0.f);
            if (row < M)
                v = *(const float4*)&A[(size_t)row * K + kb + k4 * 4];
            As[k4 * 4 + 0][m] = v.x;
            As[k4 * 4 + 1][m] = v.y;
            As[k4 * 4 + 2][m] = v.z;
            As[k4 * 4 + 3][m] = v.w;
        }
#pragma unroll
        for (int i = 0; i < 4; i++) {
            int f  = tid + i * 256;        // 0..1023 float4 slots
            int kk = f >> 5;
            int c4 = f & 31;
            *(float4*)&Ws[kk][c4 * 4] =
                *(const float4*)&W[(size_t)(kb + kk) * NW + n0 + c4 * 4];
        }
        __syncthreads();

#pragma unroll
        for (int kk = 0; kk < 32; kk++) {
            float4 w  = *(float4*)&Ws[kk][cg * 4];
            float4 al = *(float4*)&As[kk][rg * 8];
            float4 ah = *(float4*)&As[kk][rg * 8 + 4];
            float a[8] = {al.x, al.y, al.z, al.w, ah.x, ah.y, ah.z, ah.w};
#pragma unroll
            for (int i = 0; i < 8; i++) {
                acc[i][0] += a[i] * w.x;
                acc[i][1] += a[i] * w.y;
                acc[i][2] += a[i] * w.z;
                acc[i][3] += a[i] * w.w;
            }
        }
        __syncthreads();
    }
}

// GEMM 0: g_xn = dinv[row] * (state @ W_gcn)
__global__ void __launch_bounds__(256)
gemm0_kernel(const float* __restrict__ state, const float* __restrict__ W_gcn, int M)
{
    float acc[8][4];
    const int m0 = blockIdx.x * 64;
    const int n0 = blockIdx.y * 128;
    gemm_core<CDIM, CDIM>(state, W_gcn, m0, n0, M, acc);

    const int rg = threadIdx.x >> 5;
    const int cg = threadIdx.x & 31;
    const int c0 = n0 + cg * 4;
#pragma unroll
    for (int i = 0; i < 8; i++) {
        int r = m0 + rg * 8 + i;
        if (r >= M) break;
        float d = g_dinv[r];
        float4 v = make_float4(acc[i][0] * d, acc[i][1] * d,
                               acc[i][2] * d, acc[i][3] * d);
        *(float4*)&g_xn[(size_t)r * CDIM + c0] = v;
    }
}

// GEMM 1: g_h1 = relu(g_y @ W1 + b1)
__global__ void __launch_bounds__(256)
gemm1_kernel(const float* __restrict__ W1, const float* __restrict__ b1, int M)
{
    float acc[8][4];
    const int m0 = blockIdx.x * 64;
    const int n0 = blockIdx.y * 128;
    gemm_core<CDIM, HDIM>(g_y, W1, m0, n0, M, acc);

    const int rg = threadIdx.x >> 5;
    const int cg = threadIdx.x & 31;
    const int c0 = n0 + cg * 4;
    float4 b = *(const float4*)&b1[c0];
#pragma unroll
    for (int i = 0; i < 8; i++) {
        int r = m0 + rg * 8 + i;
        if (r >= M) break;
        float4 v;
        v.x = fmaxf(acc[i][0] + b.x, 0.f);
        v.y = fmaxf(acc[i][1] + b.y, 0.f);
        v.z = fmaxf(acc[i][2] + b.z, 0.f);
        v.w = fmaxf(acc[i][3] + b.w, 0.f);
        *(float4*)&g_h1[(size_t)r * HDIM + c0] = v;
    }
}

// GEMM 2: out[r] += sum_j relu((g_h1 @ W2 + b2))[r][j] * W3[j]
__global__ void __launch_bounds__(256)
gemm2_kernel(const float* __restrict__ W2, const float* __restrict__ b2,
             const float* __restrict__ W3, float* __restrict__ out, int M)
{
    float acc[8][4];
    const int m0 = blockIdx.x * 64;
    const int n0 = blockIdx.y * 128;
    gemm_core<HDIM, HDIM>(g_h1, W2, m0, n0, M, acc);

    const int rg = threadIdx.x >> 5;
    const int cg = threadIdx.x & 31;
    const int c0 = n0 + cg * 4;
    float4 b  = *(const float4*)&b2[c0];
    float4 w3 = *(const float4*)&W3[c0];
#pragma unroll
    for (int i = 0; i < 8; i++) {
        float p = fmaxf(acc[i][0] + b.x, 0.f) * w3.x
                + fmaxf(acc[i][1] + b.y, 0.f) * w3.y
                + fmaxf(acc[i][2] + b.z, 0.f) * w3.z
                + fmaxf(acc[i][3] + b.w, 0.f) * w3.w;
#pragma unroll
        for (int s = 16; s > 0; s >>= 1)
            p += __shfl_xor_sync(0xffffffffu, p, s);
        int r = m0 + rg * 8 + i;
        if (cg == 0 && r < M) atomicAdd(&out[r], p);
    }
}

// ---------------- fused CSR aggregate + norm + bias + relu + residual + readout
// One warp per output row b; lane covers 4 of 128 channels.
__global__ void readout_kernel(const float* __restrict__ state,
                               const float* __restrict__ action,
                               const float* __restrict__ b_gcn, int B)
{
    int idx  = blockIdx.x * blockDim.x + threadIdx.x;   // B * 32 threads
    int b    = idx >> 5;
    int lane = idx & 31;
    if (b >= B) return;
    int c0 = lane * 4;
    float4 bg = *(const float4*)&b_gcn[c0];
    float4 y  = make_float4(0.f, 0.f, 0.f, 0.f);
#pragma unroll
    for (int a = 0; a < ADIM; a++) {
        int n    = b * ADIM + a;
        float w  = action[b * ADIM + a] * 10.0f;
        float dn = g_dinv[n];
        // self-loop term + CSR-gathered neighbor sum of xn rows
        float4 agg = *(const float4*)&g_xn[(size_t)n * CDIM + c0];
        int st  = g_rowptr[n];
        int cnt = g_deg[n];
        for (int k = 0; k < cnt; k++) {
            int s = g_col[st + k];
            float4 v = *(const float4*)&g_xn[(size_t)s * CDIM + c0];
            agg.x += v.x; agg.y += v.y; agg.z += v.z; agg.w += v.w;
        }
        float4 stt = *(const float4*)&state[(size_t)n * CDIM + c0];
        y.x += w * (fmaxf(dn * agg.x + bg.x, 0.f) + stt.x);
        y.y += w * (fmaxf(dn * agg.y + bg.y, 0.f) + stt.y);
        y.z += w * (fmaxf(dn * agg.z + bg.z, 0.f) + stt.z);
        y.w += w * (fmaxf(dn * agg.w + bg.w, 0.f) + stt.w);
    }
    *(float4*)&g_y[(size_t)b * CDIM + c0] = y;
}

// ---------------- launch -----------------------------------------------------
extern "C" void kernel_launch(void* const* d_in, const int* in_sizes, int n_in,
                              void* d_out, int out_size)
{
    const float* state  = (const float*)d_in[0];
    const int*   ei     = (const int*)d_in[1];   // int32! (JAX x64 disabled)
    const float* action = (const float*)d_in[2];
    const float* W_gcn  = (const float*)d_in[3];
    const float* b_gcn  = (const float*)d_in[4];
    const float* W1     = (const float*)d_in[5];
    const float* b1     = (const float*)d_in[6];
    const float* W2     = (const float*)d_in[7];
    const float* b2     = (const float*)d_in[8];
    const float* W3     = (const float*)d_in[9];
    const float* b3     = (const float*)d_in[10];
    float* out = (float*)d_out;

    const int N = in_sizes[0] / CDIM;   // 500000
    const int E = in_sizes[1] / 2;      // 600000
    const int B = N / ADIM;             // 50000

    const int* esrc = ei;
    const int* edst = ei + E;

    const int NB = (N + 1023) / 1024;   // scan blocks (489)

    // 1) degrees + dinv
    zero_deg_kernel <<<(N + 255) / 256, 256>>>(N);
    count_deg_kernel<<<(E + 255) / 256, 256>>>(edst, E, N);
    dinv_kernel     <<<(N + 255) / 256, 256>>>(N);

    // 2) CSR build: rowptr = exclusive-scan(deg); col[pos] = src
    scan1_kernel<<<NB, 256>>>(N);
    scan2_kernel<<<1, 512>>>(NB);
    scan3_kernel<<<NB, 256>>>(N);
    fill_kernel <<<(E + 255) / 256, 256>>>(esrc, edst, E, N);

    // 3) xn = dinv * (state @ W_gcn)
    {
        dim3 grid((N + 63) / 64, CDIM / 128);
        gemm0_kernel<<<grid, 256>>>(state, W_gcn, N);
    }

    // 4) fused aggregate + readout -> y [B,128]
    {
        long long threads = (long long)B * 32;
        readout_kernel<<<(int)((threads + 255) / 256), 256>>>(state, action, b_gcn, B);
    }

    // 5) h1 = relu(y @ W1 + b1)  [B,256]
    {
        dim3 grid((B + 63) / 64, HDIM / 128);
        gemm1_kernel<<<grid, 256>>>(W1, b1, B);
    }

    // 6) out = relu(h1 @ W2 + b2) @ W3 + b3  (fused, atomic reduce)
    init_out_kernel<<<(B + 255) / 256, 256>>>(out, b3, B);
    {
        dim3 grid((B + 63) / 64, HDIM / 128);
        gemm2_kernel<<<grid, 256>>>(W2, b2, W3, out, B);
    }
}

// round 6
// speedup vs baseline: 1.0293x; 1.0293x over previous
#include <cuda_runtime.h>
#include <mma.h>
#include <cstdint>

using namespace nvcuda;

#define NNODES 500000
#define CDIM   128
#define HDIM   256
#define ADIM   10
#define BROWS  (NNODES / ADIM)
#define EMAX   600000

// ---------------- scratch (device globals; no allocations allowed) ----------
__device__ __align__(16) float g_xn [(size_t)NNODES * CDIM];  // dinv[row]*(state@W_gcn)
__device__ __align__(16) float g_y  [(size_t)BROWS * CDIM];   // action-weighted readout
__device__ __align__(16) float g_h1 [(size_t)BROWS * HDIM];   // relu(y@W1+b1)
__device__ int   g_deg[NNODES];
__device__ float g_dinv[NNODES];
__device__ int   g_rowptr[NNODES];
__device__ int   g_cursor[NNODES];
__device__ int   g_col[EMAX];
__device__ int   g_bsum[1024];

// ---------------- small kernels ---------------------------------------------
__global__ void zero_deg_kernel(int n) {
    int i = blockIdx.x * blockDim.x + threadIdx.x;
    if (i < n) g_deg[i] = 0;
}
__global__ void count_deg_kernel(const int* __restrict__ dst, int E, int N) {
    int e = blockIdx.x * blockDim.x + threadIdx.x;
    if (e < E) {
        int d = dst[e];
        if (d >= 0 && d < N) atomicAdd(&g_deg[d], 1);
    }
}
__global__ void dinv_kernel(int n) {
    int i = blockIdx.x * blockDim.x + threadIdx.x;
    if (i < n) g_dinv[i] = rsqrtf((float)(g_deg[i] + 1));
}
__global__ void init_out_kernel(float* __restrict__ out, const float* __restrict__ b3, int B) {
    int i = blockIdx.x * blockDim.x + threadIdx.x;
    if (i < B) out[i] = b3[0];
}

// ---------------- prefix scan (3 kernels) ------------------------------------
__global__ void __launch_bounds__(256) scan1_kernel(int n) {
    __shared__ int warp_sums[8];
    const int tid = threadIdx.x, lane = tid & 31, wid = tid >> 5;
    const int gbase = blockIdx.x * 1024 + tid * 4;
    int v[4]; int t = 0;
#pragma unroll
    for (int j = 0; j < 4; j++) { v[j] = (gbase + j < n) ? g_deg[gbase + j] : 0; t += v[j]; }
    int inc = t;
#pragma unroll
    for (int o = 1; o < 32; o <<= 1) { int x = __shfl_up_sync(~0u, inc, o); if (lane >= o) inc += x; }
    if (lane == 31) warp_sums[wid] = inc;
    __syncthreads();
    if (wid == 0) {
        int ws = (lane < 8) ? warp_sums[lane] : 0;
#pragma unroll
        for (int o = 1; o < 8; o <<= 1) { int x = __shfl_up_sync(~0u, ws, o); if (lane >= o) ws += x; }
        if (lane < 8) warp_sums[lane] = ws;
    }
    __syncthreads();
    int block_excl = (wid > 0) ? warp_sums[wid - 1] : 0;
    int run = block_excl + inc - t;
#pragma unroll
    for (int j = 0; j < 4; j++) { if (gbase + j < n) g_rowptr[gbase + j] = run; run += v[j]; }
    if (tid == 0) g_bsum[blockIdx.x] = warp_sums[7];
}
__global__ void __launch_bounds__(512) scan2_kernel(int nb) {
    __shared__ int sh[512];
    const int tid = threadIdx.x;
    int v = (tid < nb) ? g_bsum[tid] : 0;
    sh[tid] = v;
    __syncthreads();
    for (int o = 1; o < 512; o <<= 1) {
        int x = (tid >= o) ? sh[tid - o] : 0;
        __syncthreads();
        sh[tid] += x;
        __syncthreads();
    }
    if (tid < nb) g_bsum[tid] = sh[tid] - v;
}
__global__ void __launch_bounds__(256) scan3_kernel(int n) {
    const int gbase = blockIdx.x * 1024 + threadIdx.x * 4;
    const int off = g_bsum[blockIdx.x];
#pragma unroll
    for (int j = 0; j < 4; j++) {
        int i = gbase + j;
        if (i < n) { int r = g_rowptr[i] + off; g_rowptr[i] = r; g_cursor[i] = r; }
    }
}
__global__ void fill_kernel(const int* __restrict__ src, const int* __restrict__ dst,
                            int E, int N) {
    int e = blockIdx.x * blockDim.x + threadIdx.x;
    if (e >= E) return;
    int d = dst[e], s = src[e];
    if (d < 0 || d >= N || s < 0 || s >= N) return;
    int pos = atomicAdd(&g_cursor[d], 1);
    if (pos >= 0 && pos < EMAX) g_col[pos] = s;
}

// ---------------- wmma tf32 GEMM: g_xn = dinv * (state @ W_gcn) --------------
// Block: 256 threads (8 warps as 2 M x 4 N). Block tile 64x128, K-chunks of 32.
// Warp tile 32x32 = 2x2 wmma 16x16x8 fragments.
// Epilogue stages C through SMEM to apply per-row dinv with coalesced STG.
#define LDA 36     // padded lead (floats) for As [64][36] — 144B rows, 16B-aligned
#define LDW 132    // padded lead for Ws [32][132] — 528B rows, 16B-aligned
#define OFF_WS (64 * LDA * 4)          // 9216 bytes
#define SMEM_MMA0 (64 * 128 * 4)       // 32768 staging >= As+Ws (26112)

__global__ void __launch_bounds__(256)
mma0_kernel(const float* __restrict__ state, const float* __restrict__ W_gcn, int M)
{
    __shared__ __align__(16) char sh[SMEM_MMA0];
    float* As    = (float*)sh;               // [64][LDA] during mainloop
    float* Ws    = (float*)(sh + OFF_WS);    // [32][LDW] during mainloop
    float* stage = (float*)sh;               // [64][128] during epilogue

    const int tid = threadIdx.x;
    const int wid = tid >> 5;
    const int m0  = blockIdx.x * 64;
    const int wm  = (wid & 1) * 32;          // warp row offset
    const int wn  = (wid >> 1) * 32;         // warp col offset

    wmma::fragment<wmma::accumulator, 16, 16, 8, float> acc[2][2];
#pragma unroll
    for (int i = 0; i < 2; i++)
#pragma unroll
        for (int j = 0; j < 2; j++) wmma::fill_fragment(acc[i][j], 0.0f);

    for (int kb = 0; kb < CDIM; kb += 32) {
        // load A tile 64x32 (512 float4 slots, 2 per thread)
#pragma unroll
        for (int i = 0; i < 2; i++) {
            int f = tid * 2 + i;
            int m = f >> 3;                  // 0..63
            int k4 = f & 7;                  // 0..7
            float4 v = make_float4(0.f, 0.f, 0.f, 0.f);
            if (m0 + m < M)
                v = *(const float4*)&state[(size_t)(m0 + m) * CDIM + kb + k4 * 4];
            *(float4*)&As[m * LDA + k4 * 4] = v;
        }
        // load W tile 32x128 (1024 float4 slots, 4 per thread)
#pragma unroll
        for (int i = 0; i < 4; i++) {
            int f = tid + i * 256;
            int k = f >> 5;                  // 0..31
            int n4 = f & 31;                 // 0..31
            *(float4*)&Ws[k * LDW + n4 * 4] =
                *(const float4*)&W_gcn[(size_t)(kb + k) * CDIM + n4 * 4];
        }
        __syncthreads();

#pragma unroll
        for (int kk = 0; kk < 32; kk += 8) {
            wmma::fragment<wmma::matrix_a, 16, 16, 8, wmma::precision::tf32, wmma::row_major> a[2];
            wmma::fragment<wmma::matrix_b, 16, 16, 8, wmma::precision::tf32, wmma::row_major> b[2];
#pragma unroll
            for (int i = 0; i < 2; i++) {
                wmma::load_matrix_sync(a[i], &As[(wm + i * 16) * LDA + kk], LDA);
#pragma unroll
                for (int t = 0; t < a[i].num_elements; t++)
                    a[i].x[t] = wmma::__float_to_tf32(a[i].x[t]);
            }
#pragma unroll
            for (int j = 0; j < 2; j++) {
                wmma::load_matrix_sync(b[j], &Ws[kk * LDW + wn + j * 16], LDW);
#pragma unroll
                for (int t = 0; t < b[j].num_elements; t++)
                    b[j].x[t] = wmma::__float_to_tf32(b[j].x[t]);
            }
#pragma unroll
            for (int i = 0; i < 2; i++)
#pragma unroll
                for (int j = 0; j < 2; j++)
                    wmma::mma_sync(acc[i][j], a[i], b[j], acc[i][j]);
        }
        __syncthreads();
    }

    // epilogue: stage -> dinv scale -> coalesced global write
#pragma unroll
    for (int i = 0; i < 2; i++)
#pragma unroll
        for (int j = 0; j < 2; j++)
            wmma::store_matrix_sync(&stage[(wm + i * 16) * 128 + wn + j * 16],
                                    acc[i][j], 128, wmma::mem_row_major);
    __syncthreads();

#pragma unroll
    for (int i = 0; i < 8; i++) {
        int f = tid + i * 256;               // 2048 float4 slots (64 rows x 32)
        int rw = f >> 5;
        int c4 = f & 31;
        int r = m0 + rw;
        if (r < M) {
            float d = g_dinv[r];
            float4 v = *(float4*)&stage[rw * 128 + c4 * 4];
            v.x *= d; v.y *= d; v.z *= d; v.w *= d;
            *(float4*)&g_xn[(size_t)r * CDIM + c4 * 4] = v;
        }
    }
}

// ---------------- fp32 tiled GEMM core (MLP head) ----------------------------
template <int K, int NW>
__device__ __forceinline__ void gemm_core(const float* __restrict__ A,
                                          const float* __restrict__ W,
                                          int m0, int n0, int M, float acc[8][4])
{
    __shared__ __align__(16) float As[32][64];
    __shared__ __align__(16) float Ws[32][128];
    const int tid = threadIdx.x, rg = tid >> 5, cg = tid & 31;
#pragma unroll
    for (int i = 0; i < 8; i++)
#pragma unroll
        for (int j = 0; j < 4; j++) acc[i][j] = 0.f;

    for (int kb = 0; kb < K; kb += 32) {
#pragma unroll
        for (int i = 0; i < 2; i++) {
            int f = tid * 2 + i, m = f & 63, k4 = f >> 6;
            int row = m0 + m;
            float4 v = make_float4(0.f, 0.f, 0.f, 0.f);
            if (row < M) v = *(const float4*)&A[(size_t)row * K + kb + k4 * 4];
            As[k4 * 4 + 0][m] = v.x; As[k4 * 4 + 1][m] = v.y;
            As[k4 * 4 + 2][m] = v.z; As[k4 * 4 + 3][m] = v.w;
        }
#pragma unroll
        for (int i = 0; i < 4; i++) {
            int f = tid + i * 256, kk = f >> 5, c4 = f & 31;
            *(float4*)&Ws[kk][c4 * 4] = *(const float4*)&W[(size_t)(kb + kk) * NW + n0 + c4 * 4];
        }
        __syncthreads();
#pragma unroll
        for (int kk = 0; kk < 32; kk++) {
            float4 w  = *(float4*)&Ws[kk][cg * 4];
            float4 al = *(float4*)&As[kk][rg * 8];
            float4 ah = *(float4*)&As[kk][rg * 8 + 4];
            float a[8] = {al.x, al.y, al.z, al.w, ah.x, ah.y, ah.z, ah.w};
#pragma unroll
            for (int i = 0; i < 8; i++) {
                acc[i][0] += a[i] * w.x; acc[i][1] += a[i] * w.y;
                acc[i][2] += a[i] * w.z; acc[i][3] += a[i] * w.w;
            }
        }
        __syncthreads();
    }
}

__global__ void __launch_bounds__(256)
gemm1_kernel(const float* __restrict__ W1, const float* __restrict__ b1, int M)
{
    float acc[8][4];
    const int m0 = blockIdx.x * 64, n0 = blockIdx.y * 128;
    gemm_core<CDIM, HDIM>(g_y, W1, m0, n0, M, acc);
    const int rg = threadIdx.x >> 5, cg = threadIdx.x & 31, c0 = n0 + cg * 4;
    float4 b = *(const float4*)&b1[c0];
#pragma unroll
    for (int i = 0; i < 8; i++) {
        int r = m0 + rg * 8 + i;
        if (r >= M) break;
        float4 v;
        v.x = fmaxf(acc[i][0] + b.x, 0.f); v.y = fmaxf(acc[i][1] + b.y, 0.f);
        v.z = fmaxf(acc[i][2] + b.z, 0.f); v.w = fmaxf(acc[i][3] + b.w, 0.f);
        *(float4*)&g_h1[(size_t)r * HDIM + c0] = v;
    }
}

__global__ void __launch_bounds__(256)
gemm2_kernel(const float* __restrict__ W2, const float* __restrict__ b2,
             const float* __restrict__ W3, float* __restrict__ out, int M)
{
    float acc[8][4];
    const int m0 = blockIdx.x * 64, n0 = blockIdx.y * 128;
    gemm_core<HDIM, HDIM>(g_h1, W2, m0, n0, M, acc);
    const int rg = threadIdx.x >> 5, cg = threadIdx.x & 31, c0 = n0 + cg * 4;
    float4 b  = *(const float4*)&b2[c0];
    float4 w3 = *(const float4*)&W3[c0];
#pragma unroll
    for (int i = 0; i < 8; i++) {
        float p = fmaxf(acc[i][0] + b.x, 0.f) * w3.x
                + fmaxf(acc[i][1] + b.y, 0.f) * w3.y
                + fmaxf(acc[i][2] + b.z, 0.f) * w3.z
                + fmaxf(acc[i][3] + b.w, 0.f) * w3.w;
#pragma unroll
        for (int s = 16; s > 0; s >>= 1) p += __shfl_xor_sync(~0u, p, s);
        int r = m0 + rg * 8 + i;
        if (cg == 0 && r < M) atomicAdd(&out[r], p);
    }
}

// ---------------- fused CSR aggregate + readout ------------------------------
__global__ void readout_kernel(const float* __restrict__ state,
                               const float* __restrict__ action,
                               const float* __restrict__ b_gcn, int B)
{
    int idx = blockIdx.x * blockDim.x + threadIdx.x;
    int b = idx >> 5, lane = idx & 31;
    if (b >= B) return;
    int c0 = lane * 4;
    float4 bg = *(const float4*)&b_gcn[c0];
    float4 y = make_float4(0.f, 0.f, 0.f, 0.f);
#pragma unroll
    for (int a = 0; a < ADIM; a++) {
        int n = b * ADIM + a;
        float w  = action[b * ADIM + a] * 10.0f;
        float dn = g_dinv[n];
        float4 agg = *(const float4*)&g_xn[(size_t)n * CDIM + c0];
        int st = g_rowptr[n], cnt = g_deg[n];
        for (int k = 0; k < cnt; k++) {
            int s = g_col[st + k];
            float4 v = *(const float4*)&g_xn[(size_t)s * CDIM + c0];
            agg.x += v.x; agg.y += v.y; agg.z += v.z; agg.w += v.w;
        }
        float4 stt = *(const float4*)&state[(size_t)n * CDIM + c0];
        y.x += w * (fmaxf(dn * agg.x + bg.x, 0.f) + stt.x);
        y.y += w * (fmaxf(dn * agg.y + bg.y, 0.f) + stt.y);
        y.z += w * (fmaxf(dn * agg.z + bg.z, 0.f) + stt.z);
        y.w += w * (fmaxf(dn * agg.w + bg.w, 0.f) + stt.w);
    }
    *(float4*)&g_y[(size_t)b * CDIM + c0] = y;
}

// ---------------- launch -----------------------------------------------------
extern "C" void kernel_launch(void* const* d_in, const int* in_sizes, int n_in,
                              void* d_out, int out_size)
{
    const float* state  = (const float*)d_in[0];
    const int*   ei     = (const int*)d_in[1];   // int32 (JAX x64 disabled)
    const float* action = (const float*)d_in[2];
    const float* W_gcn  = (const float*)d_in[3];
    const float* b_gcn  = (const float*)d_in[4];
    const float* W1     = (const float*)d_in[5];
    const float* b1     = (const float*)d_in[6];
    const float* W2     = (const float*)d_in[7];
    const float* b2     = (const float*)d_in[8];
    const float* W3     = (const float*)d_in[9];
    const float* b3     = (const float*)d_in[10];
    float* out = (float*)d_out;

    const int N = in_sizes[0] / CDIM;
    const int E = in_sizes[1] / 2;
    const int B = N / ADIM;

    const int* esrc = ei;
    const int* edst = ei + E;
    const int NB = (N + 1023) / 1024;

    // 1) degrees + dinv
    zero_deg_kernel <<<(N + 255) / 256, 256>>>(N);
    count_deg_kernel<<<(E + 255) / 256, 256>>>(edst, E, N);
    dinv_kernel     <<<(N + 255) / 256, 256>>>(N);

    // 2) CSR build
    scan1_kernel<<<NB, 256>>>(N);
    scan2_kernel<<<1, 512>>>(NB);
    scan3_kernel<<<NB, 256>>>(N);
    fill_kernel <<<(E + 255) / 256, 256>>>(esrc, edst, E, N);

    // 3) xn = dinv * (state @ W_gcn)  -- wmma tf32
    mma0_kernel<<<(N + 63) / 64, 256>>>(state, W_gcn, N);

    // 4) fused aggregate + readout -> y [B,128]
    {
        long long threads = (long long)B * 32;
        readout_kernel<<<(int)((threads + 255) / 256), 256>>>(state, action, b_gcn, B);
    }

    // 5) h1 = relu(y @ W1 + b1)
    {
        dim3 grid((B + 63) / 64, HDIM / 128);
        gemm1_kernel<<<grid, 256>>>(W1, b1, B);
    }

    // 6) out = relu(h1 @ W2 + b2) @ W3 + b3
    init_out_kernel<<<(B + 255) / 256, 256>>>(out, b3, B);
    {
        dim3 grid((B + 63) / 64, HDIM / 128);
        gemm2_kernel<<<grid, 256>>>(W2, b2, W3, out, B);
    }
}

// round 7
// speedup vs baseline: 1.1064x; 1.0749x over previous
#include <cuda_runtime.h>
#include <mma.h>
#include <cstdint>

using namespace nvcuda;

#define NNODES 500000
#define CDIM   128
#define HDIM   256
#define ADIM   10
#define BROWS  (NNODES / ADIM)
#define EMAX   600000

// ---------------- scratch (device globals) -----------------------------------
__device__ __align__(16) float g_xn [(size_t)NNODES * CDIM];
__device__ __align__(16) float g_y  [(size_t)BROWS * CDIM];
__device__ __align__(16) float g_h1 [(size_t)BROWS * HDIM];
__device__ int   g_deg[NNODES];
__device__ int   g_rowptr[NNODES];
__device__ int   g_cursor[NNODES];
__device__ int   g_col[EMAX];
__device__ int   g_bsum[1024];

// ---------------- small kernels ----------------------------------------------
__global__ void zero_deg_kernel(int n) {
    int i = blockIdx.x * blockDim.x + threadIdx.x;
    if (i < n) g_deg[i] = 0;
}
__global__ void count_deg_kernel(const int* __restrict__ dst, int E, int N) {
    int e = blockIdx.x * blockDim.x + threadIdx.x;
    if (e < E) {
        int d = dst[e];
        if (d >= 0 && d < N) atomicAdd(&g_deg[d], 1);
    }
}
__global__ void init_out_kernel(float* __restrict__ out, const float* __restrict__ b3, int B) {
    int i = blockIdx.x * blockDim.x + threadIdx.x;
    if (i < B) out[i] = b3[0];
}

// ---------------- prefix scan (3 kernels) -------------------------------------
__global__ void __launch_bounds__(256) scan1_kernel(int n) {
    __shared__ int warp_sums[8];
    const int tid = threadIdx.x, lane = tid & 31, wid = tid >> 5;
    const int gbase = blockIdx.x * 1024 + tid * 4;
    int v[4]; int t = 0;
#pragma unroll
    for (int j = 0; j < 4; j++) { v[j] = (gbase + j < n) ? g_deg[gbase + j] : 0; t += v[j]; }
    int inc = t;
#pragma unroll
    for (int o = 1; o < 32; o <<= 1) { int x = __shfl_up_sync(~0u, inc, o); if (lane >= o) inc += x; }
    if (lane == 31) warp_sums[wid] = inc;
    __syncthreads();
    if (wid == 0) {
        int ws = (lane < 8) ? warp_sums[lane] : 0;
#pragma unroll
        for (int o = 1; o < 8; o <<= 1) { int x = __shfl_up_sync(~0u, ws, o); if (lane >= o) ws += x; }
        if (lane < 8) warp_sums[lane] = ws;
    }
    __syncthreads();
    int block_excl = (wid > 0) ? warp_sums[wid - 1] : 0;
    int run = block_excl + inc - t;
#pragma unroll
    for (int j = 0; j < 4; j++) { if (gbase + j < n) g_rowptr[gbase + j] = run; run += v[j]; }
    if (tid == 0) g_bsum[blockIdx.x] = warp_sums[7];
}
__global__ void __launch_bounds__(512) scan2_kernel(int nb) {
    __shared__ int sh[512];
    const int tid = threadIdx.x;
    int v = (tid < nb) ? g_bsum[tid] : 0;
    sh[tid] = v;
    __syncthreads();
    for (int o = 1; o < 512; o <<= 1) {
        int x = (tid >= o) ? sh[tid - o] : 0;
        __syncthreads();
        sh[tid] += x;
        __syncthreads();
    }
    if (tid < nb) g_bsum[tid] = sh[tid] - v;
}
__global__ void __launch_bounds__(256) scan3_kernel(int n) {
    const int gbase = blockIdx.x * 1024 + threadIdx.x * 4;
    const int off = g_bsum[blockIdx.x];
#pragma unroll
    for (int j = 0; j < 4; j++) {
        int i = gbase + j;
        if (i < n) { int r = g_rowptr[i] + off; g_rowptr[i] = r; g_cursor[i] = r; }
    }
}
__global__ void fill_kernel(const int* __restrict__ src, const int* __restrict__ dst,
                            int E, int N) {
    int e = blockIdx.x * blockDim.x + threadIdx.x;
    if (e >= E) return;
    int d = dst[e], s = src[e];
    if (d < 0 || d >= N || s < 0 || s >= N) return;
    int pos = atomicAdd(&g_cursor[d], 1);
    if (pos >= 0 && pos < EMAX) g_col[pos] = s;
}

// ---------------- wmma tf32 GEMM core -----------------------------------------
// Block 256 thr (8 warps, 2Mx4N), tile 64x128, K-chunks of 32, warp tile 32x32.
#define LDA 36
#define LDW 132
#define OFF_WS (64 * LDA * 4)
#define SMEM_GEMM (64 * 128 * 4)   // 32 KB; staging overlays As+Ws (26112 B)

template <int K, int NW>
__device__ __forceinline__ void wmma_core(
    const float* __restrict__ A, const float* __restrict__ W,
    char* sh, int m0, int n0, int M,
    wmma::fragment<wmma::accumulator, 16, 16, 8, float> acc[2][2])
{
    float* As = (float*)sh;
    float* Ws = (float*)(sh + OFF_WS);
    const int tid = threadIdx.x;
    const int wid = tid >> 5;
    const int wm  = (wid & 1) * 32;
    const int wn  = (wid >> 1) * 32;

#pragma unroll
    for (int i = 0; i < 2; i++)
#pragma unroll
        for (int j = 0; j < 2; j++) wmma::fill_fragment(acc[i][j], 0.0f);

    for (int kb = 0; kb < K; kb += 32) {
#pragma unroll
        for (int i = 0; i < 2; i++) {
            int f = tid * 2 + i;
            int m = f >> 3, k4 = f & 7;
            float4 v = make_float4(0.f, 0.f, 0.f, 0.f);
            if (m0 + m < M)
                v = *(const float4*)&A[(size_t)(m0 + m) * K + kb + k4 * 4];
            *(float4*)&As[m * LDA + k4 * 4] = v;
        }
#pragma unroll
        for (int i = 0; i < 4; i++) {
            int f = tid + i * 256;
            int k = f >> 5, n4 = f & 31;
            *(float4*)&Ws[k * LDW + n4 * 4] =
                *(const float4*)&W[(size_t)(kb + k) * NW + n0 + n4 * 4];
        }
        __syncthreads();

#pragma unroll
        for (int kk = 0; kk < 32; kk += 8) {
            wmma::fragment<wmma::matrix_a, 16, 16, 8, wmma::precision::tf32, wmma::row_major> a[2];
            wmma::fragment<wmma::matrix_b, 16, 16, 8, wmma::precision::tf32, wmma::row_major> b[2];
#pragma unroll
            for (int i = 0; i < 2; i++) {
                wmma::load_matrix_sync(a[i], &As[(wm + i * 16) * LDA + kk], LDA);
#pragma unroll
                for (int t = 0; t < a[i].num_elements; t++)
                    a[i].x[t] = wmma::__float_to_tf32(a[i].x[t]);
            }
#pragma unroll
            for (int j = 0; j < 2; j++) {
                wmma::load_matrix_sync(b[j], &Ws[kk * LDW + wn + j * 16], LDW);
#pragma unroll
                for (int t = 0; t < b[j].num_elements; t++)
                    b[j].x[t] = wmma::__float_to_tf32(b[j].x[t]);
            }
#pragma unroll
            for (int i = 0; i < 2; i++)
#pragma unroll
                for (int j = 0; j < 2; j++)
                    wmma::mma_sync(acc[i][j], a[i], b[j], acc[i][j]);
        }
        __syncthreads();
    }
}

__device__ __forceinline__ void stage_acc(
    char* sh, wmma::fragment<wmma::accumulator, 16, 16, 8, float> acc[2][2])
{
    float* stage = (float*)sh;
    const int wid = threadIdx.x >> 5;
    const int wm  = (wid & 1) * 32;
    const int wn  = (wid >> 1) * 32;
#pragma unroll
    for (int i = 0; i < 2; i++)
#pragma unroll
        for (int j = 0; j < 2; j++)
            wmma::store_matrix_sync(&stage[(wm + i * 16) * 128 + wn + j * 16],
                                    acc[i][j], 128, wmma::mem_row_major);
    __syncthreads();
}

// GEMM 0: g_xn = rsqrt(deg+1)[row] * (state @ W_gcn)   (K=128, NW=128)
__global__ void __launch_bounds__(256)
mma0_kernel(const float* __restrict__ state, const float* __restrict__ W_gcn, int M)
{
    __shared__ __align__(16) char sh[SMEM_GEMM];
    wmma::fragment<wmma::accumulator, 16, 16, 8, float> acc[2][2];
    const int m0 = blockIdx.x * 64;
    wmma_core<CDIM, CDIM>(state, W_gcn, sh, m0, 0, M, acc);
    stage_acc(sh, acc);
    float* stage = (float*)sh;
    const int tid = threadIdx.x;
#pragma unroll
    for (int i = 0; i < 8; i++) {
        int f = tid + i * 256;
        int rw = f >> 5, c4 = f & 31;
        int r = m0 + rw;
        if (r < M) {
            float d = rsqrtf((float)(g_deg[r] + 1));
            float4 v = *(float4*)&stage[rw * 128 + c4 * 4];
            v.x *= d; v.y *= d; v.z *= d; v.w *= d;
            *(float4*)&g_xn[(size_t)r * CDIM + c4 * 4] = v;
        }
    }
}

// GEMM 1: g_h1 = relu(g_y @ W1 + b1)   (K=128, NW=256, 2 n-blocks)
__global__ void __launch_bounds__(256)
gemm1_kernel(const float* __restrict__ W1, const float* __restrict__ b1, int M)
{
    __shared__ __align__(16) char sh[SMEM_GEMM];
    wmma::fragment<wmma::accumulator, 16, 16, 8, float> acc[2][2];
    const int m0 = blockIdx.x * 64, n0 = blockIdx.y * 128;
    wmma_core<CDIM, HDIM>(g_y, W1, sh, m0, n0, M, acc);
    stage_acc(sh, acc);
    float* stage = (float*)sh;
    const int tid = threadIdx.x;
#pragma unroll
    for (int i = 0; i < 8; i++) {
        int f = tid + i * 256;
        int rw = f >> 5, c4 = f & 31;
        int r = m0 + rw;
        if (r < M) {
            float4 b = *(const float4*)&b1[n0 + c4 * 4];
            float4 v = *(float4*)&stage[rw * 128 + c4 * 4];
            v.x = fmaxf(v.x + b.x, 0.f); v.y = fmaxf(v.y + b.y, 0.f);
            v.z = fmaxf(v.z + b.z, 0.f); v.w = fmaxf(v.w + b.w, 0.f);
            *(float4*)&g_h1[(size_t)r * HDIM + n0 + c4 * 4] = v;
        }
    }
}

// GEMM 2: out[r] += sum_j relu((g_h1 @ W2 + b2))[r][j] * W3[j]  (K=256, NW=256)
__global__ void __launch_bounds__(256)
gemm2_kernel(const float* __restrict__ W2, const float* __restrict__ b2,
             const float* __restrict__ W3, float* __restrict__ out, int M)
{
    __shared__ __align__(16) char sh[SMEM_GEMM];
    wmma::fragment<wmma::accumulator, 16, 16, 8, float> acc[2][2];
    const int m0 = blockIdx.x * 64, n0 = blockIdx.y * 128;
    wmma_core<HDIM, HDIM>(g_h1, W2, sh, m0, n0, M, acc);
    stage_acc(sh, acc);
    float* stage = (float*)sh;
    const int wid = threadIdx.x >> 5, lane = threadIdx.x & 31;
    const int c0 = n0 + lane * 4;
    float4 b  = *(const float4*)&b2[c0];
    float4 w3 = *(const float4*)&W3[c0];
#pragma unroll
    for (int i = 0; i < 8; i++) {
        int rw = wid * 8 + i;
        float4 v = *(float4*)&stage[rw * 128 + lane * 4];
        float p = fmaxf(v.x + b.x, 0.f) * w3.x
                + fmaxf(v.y + b.y, 0.f) * w3.y
                + fmaxf(v.z + b.z, 0.f) * w3.z
                + fmaxf(v.w + b.w, 0.f) * w3.w;
#pragma unroll
        for (int s = 16; s > 0; s >>= 1) p += __shfl_xor_sync(~0u, p, s);
        int r = m0 + rw;
        if (lane == 0 && r < M) atomicAdd(&out[r], p);
    }
}

// ---------------- fused CSR aggregate + readout -------------------------------
__global__ void readout_kernel(const float* __restrict__ state,
                               const float* __restrict__ action,
                               const float* __restrict__ b_gcn, int B)
{
    int idx = blockIdx.x * blockDim.x + threadIdx.x;
    int b = idx >> 5, lane = idx & 31;
    if (b >= B) return;
    int c0 = lane * 4;
    float4 bg = *(const float4*)&b_gcn[c0];
    float4 y = make_float4(0.f, 0.f, 0.f, 0.f);
#pragma unroll
    for (int a = 0; a < ADIM; a++) {
        int n = b * ADIM + a;
        float w  = action[b * ADIM + a] * 10.0f;
        int cnt = g_deg[n];
        float dn = rsqrtf((float)(cnt + 1));
        float4 agg = *(const float4*)&g_xn[(size_t)n * CDIM + c0];
        int st = g_rowptr[n];
        for (int k = 0; k < cnt; k++) {
            int s = g_col[st + k];
            float4 v = *(const float4*)&g_xn[(size_t)s * CDIM + c0];
            agg.x += v.x; agg.y += v.y; agg.z += v.z; agg.w += v.w;
        }
        float4 stt = *(const float4*)&state[(size_t)n * CDIM + c0];
        y.x += w * (fmaxf(dn * agg.x + bg.x, 0.f) + stt.x);
        y.y += w * (fmaxf(dn * agg.y + bg.y, 0.f) + stt.y);
        y.z += w * (fmaxf(dn * agg.z + bg.z, 0.f) + stt.z);
        y.w += w * (fmaxf(dn * agg.w + bg.w, 0.f) + stt.w);
    }
    *(float4*)&g_y[(size_t)b * CDIM + c0] = y;
}

// ---------------- launch ------------------------------------------------------
extern "C" void kernel_launch(void* const* d_in, const int* in_sizes, int n_in,
                              void* d_out, int out_size)
{
    const float* state  = (const float*)d_in[0];
    const int*   ei     = (const int*)d_in[1];   // int32 (JAX x64 disabled)
    const float* action = (const float*)d_in[2];
    const float* W_gcn  = (const float*)d_in[3];
    const float* b_gcn  = (const float*)d_in[4];
    const float* W1     = (const float*)d_in[5];
    const float* b1     = (const float*)d_in[6];
    const float* W2     = (const float*)d_in[7];
    const float* b2     = (const float*)d_in[8];
    const float* W3     = (const float*)d_in[9];
    const float* b3     = (const float*)d_in[10];
    float* out = (float*)d_out;

    const int N = in_sizes[0] / CDIM;
    const int E = in_sizes[1] / 2;
    const int B = N / ADIM;

    const int* esrc = ei;
    const int* edst = ei + E;
    const int NB = (N + 1023) / 1024;

    // launches ordered so ncu (-s 5 -c 1) captures mma0_kernel (6th launch)
    zero_deg_kernel <<<(N + 255) / 256, 256>>>(N);                 // 1
    count_deg_kernel<<<(E + 255) / 256, 256>>>(edst, E, N);        // 2
    scan1_kernel<<<NB, 256>>>(N);                                  // 3
    scan2_kernel<<<1, 512>>>(NB);                                  // 4
    scan3_kernel<<<NB, 256>>>(N);                                  // 5
    mma0_kernel<<<(N + 63) / 64, 256>>>(state, W_gcn, N);          // 6 <- profiled
    fill_kernel <<<(E + 255) / 256, 256>>>(esrc, edst, E, N);      // 7
    {
        long long threads = (long long)B * 32;
        readout_kernel<<<(int)((threads + 255) / 256), 256>>>(state, action, b_gcn, B);
    }
    {
        dim3 grid((B + 63) / 64, HDIM / 128);
        gemm1_kernel<<<grid, 256>>>(W1, b1, B);
    }
    init_out_kernel<<<(B + 255) / 256, 256>>>(out, b3, B);
    {
        dim3 grid((B + 63) / 64, HDIM / 128);
        gemm2_kernel<<<grid, 256>>>(W2, b2, W3, out, B);
    }
}

// round 8
// speedup vs baseline: 1.2338x; 1.1152x over previous
#include <cuda_runtime.h>
#include <mma.h>
#include <cstdint>

using namespace nvcuda;

#define NNODES 500000
#define CDIM   128
#define HDIM   256
#define ADIM   10
#define BROWS  (NNODES / ADIM)
#define EMAX   600000

// ---------------- scratch (device globals) -----------------------------------
__device__ __align__(16) float g_xn [(size_t)NNODES * CDIM];
__device__ __align__(16) float g_y  [(size_t)BROWS * CDIM];
__device__ __align__(16) float g_h1 [(size_t)BROWS * HDIM];
__device__ int   g_deg[NNODES];
__device__ int   g_rowptr[NNODES];
__device__ int   g_cursor[NNODES];
__device__ int   g_col[EMAX];
__device__ int   g_bsum[1024];

// ---------------- small kernels ----------------------------------------------
__global__ void zero_deg_kernel(int n) {
    int i = blockIdx.x * blockDim.x + threadIdx.x;
    if (i < n) g_deg[i] = 0;
}
__global__ void count_deg_kernel(const int* __restrict__ dst, int E, int N) {
    int e = blockIdx.x * blockDim.x + threadIdx.x;
    if (e < E) {
        int d = dst[e];
        if (d >= 0 && d < N) atomicAdd(&g_deg[d], 1);
    }
}
__global__ void init_out_kernel(float* __restrict__ out, const float* __restrict__ b3, int B) {
    int i = blockIdx.x * blockDim.x + threadIdx.x;
    if (i < B) out[i] = b3[0];
}

// ---------------- prefix scan (3 kernels) -------------------------------------
__global__ void __launch_bounds__(256) scan1_kernel(int n) {
    __shared__ int warp_sums[8];
    const int tid = threadIdx.x, lane = tid & 31, wid = tid >> 5;
    const int gbase = blockIdx.x * 1024 + tid * 4;
    int v[4]; int t = 0;
#pragma unroll
    for (int j = 0; j < 4; j++) { v[j] = (gbase + j < n) ? g_deg[gbase + j] : 0; t += v[j]; }
    int inc = t;
#pragma unroll
    for (int o = 1; o < 32; o <<= 1) { int x = __shfl_up_sync(~0u, inc, o); if (lane >= o) inc += x; }
    if (lane == 31) warp_sums[wid] = inc;
    __syncthreads();
    if (wid == 0) {
        int ws = (lane < 8) ? warp_sums[lane] : 0;
#pragma unroll
        for (int o = 1; o < 8; o <<= 1) { int x = __shfl_up_sync(~0u, ws, o); if (lane >= o) ws += x; }
        if (lane < 8) warp_sums[lane] = ws;
    }
    __syncthreads();
    int block_excl = (wid > 0) ? warp_sums[wid - 1] : 0;
    int run = block_excl + inc - t;
#pragma unroll
    for (int j = 0; j < 4; j++) { if (gbase + j < n) g_rowptr[gbase + j] = run; run += v[j]; }
    if (tid == 0) g_bsum[blockIdx.x] = warp_sums[7];
}
__global__ void __launch_bounds__(512) scan2_kernel(int nb) {
    __shared__ int sh[512];
    const int tid = threadIdx.x;
    int v = (tid < nb) ? g_bsum[tid] : 0;
    sh[tid] = v;
    __syncthreads();
    for (int o = 1; o < 512; o <<= 1) {
        int x = (tid >= o) ? sh[tid - o] : 0;
        __syncthreads();
        sh[tid] += x;
        __syncthreads();
    }
    if (tid < nb) g_bsum[tid] = sh[tid] - v;
}
__global__ void __launch_bounds__(256) scan3_kernel(int n) {
    const int gbase = blockIdx.x * 1024 + threadIdx.x * 4;
    const int off = g_bsum[blockIdx.x];
#pragma unroll
    for (int j = 0; j < 4; j++) {
        int i = gbase + j;
        if (i < n) { int r = g_rowptr[i] + off; g_rowptr[i] = r; g_cursor[i] = r; }
    }
}
__global__ void fill_kernel(const int* __restrict__ src, const int* __restrict__ dst,
                            int E, int N) {
    int e = blockIdx.x * blockDim.x + threadIdx.x;
    if (e >= E) return;
    int d = dst[e], s = src[e];
    if (d < 0 || d >= N || s < 0 || s >= N) return;
    int pos = atomicAdd(&g_cursor[d], 1);
    if (pos >= 0 && pos < EMAX) g_col[pos] = s;
}

// ---------------- wmma tf32 GEMM core v2 ---------------------------------------
// Block 256 thr (8 warps, 2Mx4N), tile 64x128, K-chunks of 32, warp tile 32x32.
// v2: tf32 conversion hoisted to SMEM store; next chunk register-prefetched so
//     LDG latency overlaps the MMA stage. Inner loop = pure LDS + HMMA.
#define LDA 36
#define LDW 132
#define OFF_WS (64 * LDA * 4)
#define SMEM_GEMM (64 * 128 * 4)   // 32 KB; staging overlays As+Ws (26112 B)

template <int K, int NW>
__device__ __forceinline__ void wmma_core(
    const float* __restrict__ A, const float* __restrict__ W,
    char* sh, int m0, int n0, int M,
    wmma::fragment<wmma::accumulator, 16, 16, 8, float> acc[2][2])
{
    float* As = (float*)sh;
    float* Ws = (float*)(sh + OFF_WS);
    const int tid = threadIdx.x;
    const int wid = tid >> 5;
    const int wm  = (wid & 1) * 32;
    const int wn  = (wid >> 1) * 32;

#pragma unroll
    for (int i = 0; i < 2; i++)
#pragma unroll
        for (int j = 0; j < 2; j++) wmma::fill_fragment(acc[i][j], 0.0f);

    float4 ra[2], rw[4];

    // prologue: load chunk 0 into registers
#pragma unroll
    for (int i = 0; i < 2; i++) {
        int f = tid * 2 + i;
        int m = f >> 3, k4 = f & 7;
        ra[i] = make_float4(0.f, 0.f, 0.f, 0.f);
        if (m0 + m < M)
            ra[i] = *(const float4*)&A[(size_t)(m0 + m) * K + k4 * 4];
    }
#pragma unroll
    for (int i = 0; i < 4; i++) {
        int f = tid + i * 256;
        int k = f >> 5, n4 = f & 31;
        rw[i] = *(const float4*)&W[(size_t)k * NW + n0 + n4 * 4];
    }

    const int nchunks = K / 32;
    for (int c = 0; c < nchunks; c++) {
        // store staged regs to SMEM with tf32 rounding (done ONCE per element)
#pragma unroll
        for (int i = 0; i < 2; i++) {
            int f = tid * 2 + i;
            int m = f >> 3, k4 = f & 7;
            float4 v = ra[i];
            v.x = wmma::__float_to_tf32(v.x); v.y = wmma::__float_to_tf32(v.y);
            v.z = wmma::__float_to_tf32(v.z); v.w = wmma::__float_to_tf32(v.w);
            *(float4*)&As[m * LDA + k4 * 4] = v;
        }
#pragma unroll
        for (int i = 0; i < 4; i++) {
            int f = tid + i * 256;
            int k = f >> 5, n4 = f & 31;
            float4 v = rw[i];
            v.x = wmma::__float_to_tf32(v.x); v.y = wmma::__float_to_tf32(v.y);
            v.z = wmma::__float_to_tf32(v.z); v.w = wmma::__float_to_tf32(v.w);
            *(float4*)&Ws[k * LDW + n4 * 4] = v;
        }
        __syncthreads();

        // prefetch next chunk (LDGs in flight during MMA below)
        if (c + 1 < nchunks) {
            int kb = (c + 1) * 32;
#pragma unroll
            for (int i = 0; i < 2; i++) {
                int f = tid * 2 + i;
                int m = f >> 3, k4 = f & 7;
                ra[i] = make_float4(0.f, 0.f, 0.f, 0.f);
                if (m0 + m < M)
                    ra[i] = *(const float4*)&A[(size_t)(m0 + m) * K + kb + k4 * 4];
            }
#pragma unroll
            for (int i = 0; i < 4; i++) {
                int f = tid + i * 256;
                int k = f >> 5, n4 = f & 31;
                rw[i] = *(const float4*)&W[(size_t)(kb + k) * NW + n0 + n4 * 4];
            }
        }

        // MMA stage: pure LDS + HMMA, no cvt
#pragma unroll
        for (int kk = 0; kk < 32; kk += 8) {
            wmma::fragment<wmma::matrix_a, 16, 16, 8, wmma::precision::tf32, wmma::row_major> a[2];
            wmma::fragment<wmma::matrix_b, 16, 16, 8, wmma::precision::tf32, wmma::row_major> b[2];
#pragma unroll
            for (int i = 0; i < 2; i++)
                wmma::load_matrix_sync(a[i], &As[(wm + i * 16) * LDA + kk], LDA);
#pragma unroll
            for (int j = 0; j < 2; j++)
                wmma::load_matrix_sync(b[j], &Ws[kk * LDW + wn + j * 16], LDW);
#pragma unroll
            for (int i = 0; i < 2; i++)
#pragma unroll
                for (int j = 0; j < 2; j++)
                    wmma::mma_sync(acc[i][j], a[i], b[j], acc[i][j]);
        }
        __syncthreads();   // protect SMEM overwrite next iter / staging reuse
    }
}

__device__ __forceinline__ void stage_acc(
    char* sh, wmma::fragment<wmma::accumulator, 16, 16, 8, float> acc[2][2])
{
    float* stage = (float*)sh;
    const int wid = threadIdx.x >> 5;
    const int wm  = (wid & 1) * 32;
    const int wn  = (wid >> 1) * 32;
#pragma unroll
    for (int i = 0; i < 2; i++)
#pragma unroll
        for (int j = 0; j < 2; j++)
            wmma::store_matrix_sync(&stage[(wm + i * 16) * 128 + wn + j * 16],
                                    acc[i][j], 128, wmma::mem_row_major);
    __syncthreads();
}

// GEMM 0: g_xn = rsqrt(deg+1)[row] * (state @ W_gcn)
__global__ void __launch_bounds__(256)
mma0_kernel(const float* __restrict__ state, const float* __restrict__ W_gcn, int M)
{
    __shared__ __align__(16) char sh[SMEM_GEMM];
    wmma::fragment<wmma::accumulator, 16, 16, 8, float> acc[2][2];
    const int m0 = blockIdx.x * 64;
    wmma_core<CDIM, CDIM>(state, W_gcn, sh, m0, 0, M, acc);
    stage_acc(sh, acc);
    float* stage = (float*)sh;
    const int tid = threadIdx.x;
#pragma unroll
    for (int i = 0; i < 8; i++) {
        int f = tid + i * 256;
        int rw = f >> 5, c4 = f & 31;
        int r = m0 + rw;
        if (r < M) {
            float d = rsqrtf((float)(g_deg[r] + 1));
            float4 v = *(float4*)&stage[rw * 128 + c4 * 4];
            v.x *= d; v.y *= d; v.z *= d; v.w *= d;
            *(float4*)&g_xn[(size_t)r * CDIM + c4 * 4] = v;
        }
    }
}

// GEMM 1: g_h1 = relu(g_y @ W1 + b1)
__global__ void __launch_bounds__(256)
gemm1_kernel(const float* __restrict__ W1, const float* __restrict__ b1, int M)
{
    __shared__ __align__(16) char sh[SMEM_GEMM];
    wmma::fragment<wmma::accumulator, 16, 16, 8, float> acc[2][2];
    const int m0 = blockIdx.x * 64, n0 = blockIdx.y * 128;
    wmma_core<CDIM, HDIM>(g_y, W1, sh, m0, n0, M, acc);
    stage_acc(sh, acc);
    float* stage = (float*)sh;
    const int tid = threadIdx.x;
#pragma unroll
    for (int i = 0; i < 8; i++) {
        int f = tid + i * 256;
        int rw = f >> 5, c4 = f & 31;
        int r = m0 + rw;
        if (r < M) {
            float4 b = *(const float4*)&b1[n0 + c4 * 4];
            float4 v = *(float4*)&stage[rw * 128 + c4 * 4];
            v.x = fmaxf(v.x + b.x, 0.f); v.y = fmaxf(v.y + b.y, 0.f);
            v.z = fmaxf(v.z + b.z, 0.f); v.w = fmaxf(v.w + b.w, 0.f);
            *(float4*)&g_h1[(size_t)r * HDIM + n0 + c4 * 4] = v;
        }
    }
}

// GEMM 2: out[r] += sum_j relu((g_h1 @ W2 + b2))[r][j] * W3[j]
__global__ void __launch_bounds__(256)
gemm2_kernel(const float* __restrict__ W2, const float* __restrict__ b2,
             const float* __restrict__ W3, float* __restrict__ out, int M)
{
    __shared__ __align__(16) char sh[SMEM_GEMM];
    wmma::fragment<wmma::accumulator, 16, 16, 8, float> acc[2][2];
    const int m0 = blockIdx.x * 64, n0 = blockIdx.y * 128;
    wmma_core<HDIM, HDIM>(g_h1, W2, sh, m0, n0, M, acc);
    stage_acc(sh, acc);
    float* stage = (float*)sh;
    const int wid = threadIdx.x >> 5, lane = threadIdx.x & 31;
    const int c0 = n0 + lane * 4;
    float4 b  = *(const float4*)&b2[c0];
    float4 w3 = *(const float4*)&W3[c0];
#pragma unroll
    for (int i = 0; i < 8; i++) {
        int rw = wid * 8 + i;
        float4 v = *(float4*)&stage[rw * 128 + lane * 4];
        float p = fmaxf(v.x + b.x, 0.f) * w3.x
                + fmaxf(v.y + b.y, 0.f) * w3.y
                + fmaxf(v.z + b.z, 0.f) * w3.z
                + fmaxf(v.w + b.w, 0.f) * w3.w;
#pragma unroll
        for (int s = 16; s > 0; s >>= 1) p += __shfl_xor_sync(~0u, p, s);
        int r = m0 + rw;
        if (lane == 0 && r < M) atomicAdd(&out[r], p);
    }
}

// ---------------- fused CSR aggregate + readout -------------------------------
__global__ void readout_kernel(const float* __restrict__ state,
                               const float* __restrict__ action,
                               const float* __restrict__ b_gcn, int B)
{
    int idx = blockIdx.x * blockDim.x + threadIdx.x;
    int b = idx >> 5, lane = idx & 31;
    if (b >= B) return;
    int c0 = lane * 4;
    float4 bg = *(const float4*)&b_gcn[c0];
    float4 y = make_float4(0.f, 0.f, 0.f, 0.f);
#pragma unroll
    for (int a = 0; a < ADIM; a++) {
        int n = b * ADIM + a;
        float w  = action[b * ADIM + a] * 10.0f;
        int cnt = g_deg[n];
        float dn = rsqrtf((float)(cnt + 1));
        float4 agg = *(const float4*)&g_xn[(size_t)n * CDIM + c0];
        int st = g_rowptr[n];
        for (int k = 0; k < cnt; k++) {
            int s = g_col[st + k];
            float4 v = *(const float4*)&g_xn[(size_t)s * CDIM + c0];
            agg.x += v.x; agg.y += v.y; agg.z += v.z; agg.w += v.w;
        }
        float4 stt = *(const float4*)&state[(size_t)n * CDIM + c0];
        y.x += w * (fmaxf(dn * agg.x + bg.x, 0.f) + stt.x);
        y.y += w * (fmaxf(dn * agg.y + bg.y, 0.f) + stt.y);
        y.z += w * (fmaxf(dn * agg.z + bg.z, 0.f) + stt.z);
        y.w += w * (fmaxf(dn * agg.w + bg.w, 0.f) + stt.w);
    }
    *(float4*)&g_y[(size_t)b * CDIM + c0] = y;
}

// ---------------- launch ------------------------------------------------------
extern "C" void kernel_launch(void* const* d_in, const int* in_sizes, int n_in,
                              void* d_out, int out_size)
{
    const float* state  = (const float*)d_in[0];
    const int*   ei     = (const int*)d_in[1];   // int32 (JAX x64 disabled)
    const float* action = (const float*)d_in[2];
    const float* W_gcn  = (const float*)d_in[3];
    const float* b_gcn  = (const float*)d_in[4];
    const float* W1     = (const float*)d_in[5];
    const float* b1     = (const float*)d_in[6];
    const float* W2     = (const float*)d_in[7];
    const float* b2     = (const float*)d_in[8];
    const float* W3     = (const float*)d_in[9];
    const float* b3     = (const float*)d_in[10];
    float* out = (float*)d_out;

    const int N = in_sizes[0] / CDIM;
    const int E = in_sizes[1] / 2;
    const int B = N / ADIM;

    const int* esrc = ei;
    const int* edst = ei + E;
    const int NB = (N + 1023) / 1024;

    zero_deg_kernel <<<(N + 255) / 256, 256>>>(N);
    count_deg_kernel<<<(E + 255) / 256, 256>>>(edst, E, N);
    scan1_kernel<<<NB, 256>>>(N);
    scan2_kernel<<<1, 512>>>(NB);
    scan3_kernel<<<NB, 256>>>(N);
    mma0_kernel<<<(N + 63) / 64, 256>>>(state, W_gcn, N);
    fill_kernel <<<(E + 255) / 256, 256>>>(esrc, edst, E, N);
    {
        long long threads = (long long)B * 32;
        readout_kernel<<<(int)((threads + 255) / 256), 256>>>(state, action, b_gcn, B);
    }
    {
        dim3 grid((B + 63) / 64, HDIM / 128);
        gemm1_kernel<<<grid, 256>>>(W1, b1, B);
    }
    init_out_kernel<<<(B + 255) / 256, 256>>>(out, b3, B);
    {
        dim3 grid((B + 63) / 64, HDIM / 128);
        gemm2_kernel<<<grid, 256>>>(W2, b2, W3, out, B);
    }
}